// round 12
// baseline (speedup 1.0000x reference)
#include <cuda_runtime.h>
#include <cuda_fp16.h>
#include <cstdint>

#define BB 8
#define NN 2000
#define EE 20
#define HH 128
#define TNODES 4
#define TROWS 80                 // 4 nodes * 20 edges per CTA tile
#define NTILES 4000              // 16000 nodes / 4

// kB smem layout (bytes)
#define SA_OFF    0              // A fp16 double buffer: 2 * 20480
#define ABUF_B    20480
#define SLOG_OFF  40960          // logits 80x132 fp32 = 42240
#define LSTRIDE   132
#define SIDX_OFF  83200          // 80 ints
#define SMEMB     83584
// transient W-build area (before the pipeline starts): WH at offset 0

// kA smem layout
#define KA_SX 0                  // x fp16 swizzled 32768
#define KA_WH 32768              // W hi fp16 swizzled 32768
#define KA_WL 65536              // W lo fp16 swizzled 32768
#define KA_SMEM 98304

__device__ float g_Vx[BB * NN * HH];

// ---------------------------------------------------------------- helpers
__device__ __forceinline__ uint32_t smem_u32(const void* p) {
    uint32_t a;
    asm("{ .reg .u64 t; cvta.to.shared.u64 t, %1; cvt.u32.u64 %0, t; }" : "=r"(a) : "l"(p));
    return a;
}
// pack two fp32 -> fp16x2 (first arg -> low half)
__device__ __forceinline__ uint32_t pack_f16(float lo, float hi) {
    uint32_t r;
    asm("cvt.rn.f16x2.f32 %0, %1, %2;" : "=r"(r) : "f"(hi), "f"(lo));
    return r;
}
__device__ __forceinline__ float f16lo(uint32_t p) {
    float f;
    asm("{ .reg .b16 l, h; mov.b32 {l, h}, %1; cvt.f32.f16 %0, l; }" : "=f"(f) : "r"(p));
    return f;
}
__device__ __forceinline__ float f16hi(uint32_t p) {
    float f;
    asm("{ .reg .b16 l, h; mov.b32 {l, h}, %1; cvt.f32.f16 %0, h; }" : "=f"(f) : "r"(p));
    return f;
}
__device__ __forceinline__ void ldsm4(uint32_t addr, uint32_t* r) {
    asm volatile("ldmatrix.sync.aligned.m8n8.x4.shared.b16 {%0,%1,%2,%3}, [%4];"
                 : "=r"(r[0]), "=r"(r[1]), "=r"(r[2]), "=r"(r[3]) : "r"(addr));
}
__device__ __forceinline__ void ldsm4t(uint32_t addr, uint32_t* r) {
    asm volatile("ldmatrix.sync.aligned.m8n8.x4.trans.shared.b16 {%0,%1,%2,%3}, [%4];"
                 : "=r"(r[0]), "=r"(r[1]), "=r"(r[2]), "=r"(r[3]) : "r"(addr));
}
__device__ __forceinline__ void mma16816(float* d, const uint32_t* a, uint32_t b0, uint32_t b1) {
    asm volatile("mma.sync.aligned.m16n8k16.row.col.f32.f16.f16.f32 "
                 "{%0,%1,%2,%3}, {%4,%5,%6,%7}, {%8,%9}, {%0,%1,%2,%3};"
                 : "+f"(d[0]), "+f"(d[1]), "+f"(d[2]), "+f"(d[3])
                 : "r"(a[0]), "r"(a[1]), "r"(a[2]), "r"(a[3]), "r"(b0), "r"(b1));
}

// swizzled fp16 256B-row offset for float4-chunk index ch4 of a 128-wide tile
__device__ __forceinline__ uint32_t swoff(int ch4) {
    int row = ch4 >> 5, c4 = ch4 & 31;
    return ((uint32_t)row << 8) + ((((uint32_t)(c4 >> 1)) ^ (row & 7)) << 4) + ((c4 & 1) << 3);
}
// fp32 float4 -> fp16, stored swizzled
__device__ __forceinline__ void cvtStoreF16(char* dst, int ch4, float4 v) {
    uint32_t sw = swoff(ch4);
    *(uint2*)(dst + sw) = make_uint2(pack_f16(v.x, v.y), pack_f16(v.z, v.w));
}
// fp32 float4 -> fp16 hi + residual lo, stored swizzled
__device__ __forceinline__ void cvtStoreHL(char* dh, char* dl, int ch4, float4 v) {
    uint32_t sw = swoff(ch4);
    uint32_t h0 = pack_f16(v.x, v.y);
    uint32_t h1 = pack_f16(v.z, v.w);
    uint32_t l0 = pack_f16(v.x - f16lo(h0), v.y - f16hi(h0));
    uint32_t l1 = pack_f16(v.z - f16lo(h1), v.w - f16hi(h1));
    *(uint2*)(dh + sw) = make_uint2(h0, h1);
    *(uint2*)(dl + sw) = make_uint2(l0, l1);
}

// ---------------------------------------------------------------------------
// Kernel A (tensor-core): per CTA, 128 rows of x. Two passes:
//   pass 0: out  = x @ Wu + bu
//   pass 1: g_Vx = x @ Wv + bv
// 512 threads / 16 warps. fp16 2-term W split, x in fp16.
// ---------------------------------------------------------------------------
__global__ void __launch_bounds__(512, 1) kA(
    const float* __restrict__ x, const float* __restrict__ Wu,
    const float* __restrict__ bu, const float* __restrict__ Wv,
    const float* __restrict__ bv, float* __restrict__ out)
{
    extern __shared__ __align__(1024) char smem[];
    const uint32_t sb = smem_u32(smem);
    const int tid = threadIdx.x;
    const int w = tid >> 5;
    const int l = tid & 31;
    const int mg = w >> 3;
    const int nc = w & 7;
    const int lrow = (l & 7) + ((l >> 3) & 1) * 8;
    const int lchk = l >> 4;
    const size_t rowBase = (size_t)blockIdx.x * 128;

    // load x tile -> fp16 swizzled  (128x128 = 4096 float4s, 8 per thread)
    {
        const float4* src = (const float4*)(x + rowBase * HH);
        #pragma unroll
        for (int q = 0; q < 8; q++) {
            int ch4 = tid + 512 * q;
            cvtStoreF16((char*)smem + KA_SX, ch4, src[ch4]);
        }
    }

    #pragma unroll 1
    for (int pass = 0; pass < 2; pass++) {
        const float* W = pass ? Wv : Wu;
        const float* bias = pass ? bv : bu;
        // build W hi/lo  (4096 float4s, 8 per thread)
        #pragma unroll
        for (int q = 0; q < 8; q++) {
            int ch4 = tid + 512 * q;
            cvtStoreHL((char*)smem + KA_WH, (char*)smem + KA_WL, ch4,
                       ((const float4*)W)[ch4]);
        }
        __syncthreads();

        float acc[4][2][4];
        #pragma unroll
        for (int mt = 0; mt < 4; mt++)
            #pragma unroll
            for (int nt = 0; nt < 2; nt++)
                #pragma unroll
                for (int q = 0; q < 4; q++) acc[mt][nt][q] = 0.f;

        #pragma unroll
        for (int ks = 0; ks < 8; ks++) {
            uint32_t bh[4], bl[4];
            {
                int row = ks * 16 + lrow;
                uint32_t off = ((uint32_t)row << 8) +
                               (((uint32_t)((nc * 2 + lchk) ^ (row & 7))) << 4);
                ldsm4t(sb + KA_WH + off, bh);
                ldsm4t(sb + KA_WL + off, bl);
            }
            #pragma unroll
            for (int mt = 0; mt < 4; mt++) {
                uint32_t a[4];
                int row = mg * 64 + mt * 16 + lrow;
                uint32_t off = ((uint32_t)row << 8) +
                               (((uint32_t)((ks * 2 + lchk) ^ (row & 7))) << 4);
                ldsm4(sb + KA_SX + off, a);
                mma16816(acc[mt][0], a, bh[0], bh[1]);
                mma16816(acc[mt][1], a, bh[2], bh[3]);
                mma16816(acc[mt][0], a, bl[0], bl[1]);
                mma16816(acc[mt][1], a, bl[2], bl[3]);
            }
        }

        float* dst = pass ? g_Vx : out;
        #pragma unroll
        for (int nt = 0; nt < 2; nt++) {
            int c0 = nc * 16 + nt * 8 + 2 * (l & 3);
            float2 b2 = *(const float2*)(bias + c0);
            #pragma unroll
            for (int mt = 0; mt < 4; mt++) {
                int r0 = mg * 64 + mt * 16 + (l >> 2);
                *(float2*)(dst + (rowBase + r0) * HH + c0) =
                    make_float2(acc[mt][nt][0] + b2.x, acc[mt][nt][1] + b2.y);
                *(float2*)(dst + (rowBase + r0 + 8) * HH + c0) =
                    make_float2(acc[mt][nt][2] + b2.x, acc[mt][nt][3] + b2.y);
            }
        }
        __syncthreads();   // W area reads done before next pass overwrites
    }
}

// ---------------------------------------------------------------------------
// Kernel B: logits = e16 @ We16 via fp16 mma (single W term). Next e-tile is
// loaded LDG->cvt fp16->STS, software-pipelined inside the mma loop (no fp32
// smem staging roundtrip). 256 threads / 8 warps, 2 CTAs/SM.
// ---------------------------------------------------------------------------
__global__ void __launch_bounds__(256, 2) kB(
    const float* __restrict__ e, const float* __restrict__ We,
    const int* __restrict__ edge_index, float* __restrict__ out)
{
    extern __shared__ __align__(1024) char smem[];
    const uint32_t sb = smem_u32(smem);
    float* sLog = (float*)(smem + SLOG_OFF);
    int*   sIdx = (int*)(smem + SIDX_OFF);
    const int tid = threadIdx.x;
    const int w = tid >> 5;
    const int l = tid & 31;
    const int lrow = (l & 7) + ((l >> 3) & 1) * 8;
    const int lchk = l >> 4;

    // ---- Build We (hi only) fp16 swizzled at offset 0 (transient) ----
    #pragma unroll
    for (int q = 0; q < 16; q++) {
        int ch4 = tid + 256 * q;     // 0..4095
        cvtStoreF16((char*)smem, ch4, ((const float4*)We)[ch4]);
    }
    __syncthreads();

    // ---- Hoist W fragments (n16 per warp, all K): 32 regs ----
    uint32_t bh[8][4];
    #pragma unroll
    for (int ks = 0; ks < 8; ks++) {
        int row = ks * 16 + lrow;
        uint32_t off = ((uint32_t)row << 8) +
                       (((uint32_t)((w * 2 + lchk) ^ (row & 7))) << 4);
        ldsm4t(sb + off, bh[ks]);
    }
    __syncthreads();   // hoists done before region is reused (A buffers live at 0)

    // ---- Prologue: first tile LDG -> cvt -> A[0] ----
    const int tile0 = blockIdx.x;
    if (tile0 < NTILES) {
        const float4* src = (const float4*)(e + (size_t)tile0 * TROWS * HH);
        char* dst = (char*)smem + SA_OFF;
        #pragma unroll
        for (int q = 0; q < 10; q++) {
            int ch4 = tid + 256 * q;
            cvtStoreF16(dst, ch4, src[ch4]);
        }
    }
    __syncthreads();

    int buf = 0;
    for (int tile = tile0; tile < NTILES; tile += gridDim.x) {
        const int ntile = tile + gridDim.x;
        const bool havenext = ntile < NTILES;
        const float4* nsrc = (const float4*)(e + (size_t)ntile * TROWS * HH);
        char* ndst = (char*)smem + SA_OFF + (buf ^ 1) * ABUF_B;

        if (tid < TROWS) sIdx[tid] = edge_index[(size_t)tile * TROWS + tid];

        // pipeline chunk 0 of next tile (2 float4 per thread per chunk)
        float4 v0, v1;
        if (havenext) { v0 = nsrc[tid]; v1 = nsrc[tid + 256]; }

        // mma mainloop: D[80 x 128], 5 m-tiles per warp, single W term;
        // next-tile convert/store woven in after every odd ks.
        float acc[5][2][4];
        #pragma unroll
        for (int mt = 0; mt < 5; mt++)
            #pragma unroll
            for (int nt = 0; nt < 2; nt++)
                #pragma unroll
                for (int q = 0; q < 4; q++) acc[mt][nt][q] = 0.f;

        const uint32_t baseA = sb + SA_OFF + buf * ABUF_B;
        #pragma unroll
        for (int ks = 0; ks < 8; ks++) {
            #pragma unroll
            for (int mt = 0; mt < 5; mt++) {
                uint32_t a[4];
                int row = mt * 16 + lrow;
                uint32_t off = ((uint32_t)row << 8) +
                               (((uint32_t)((ks * 2 + lchk) ^ (row & 7))) << 4);
                ldsm4(baseA + off, a);
                mma16816(acc[mt][0], a, bh[ks][0], bh[ks][1]);
                mma16816(acc[mt][1], a, bh[ks][2], bh[ks][3]);
            }
            if (ks & 1) {
                const int c = ks >> 1;          // 0..3
                if (havenext) {
                    cvtStoreF16(ndst, tid + 256 * (2 * c), v0);
                    cvtStoreF16(ndst, tid + 256 * (2 * c + 1), v1);
                    if (c < 4) {
                        v0 = nsrc[tid + 256 * (2 * c + 2)];
                        v1 = nsrc[tid + 256 * (2 * c + 3)];
                    }
                }
            }
        }
        // final chunk (c = 4)
        if (havenext) {
            cvtStoreF16(ndst, tid + 256 * 8, v0);
            cvtStoreF16(ndst, tid + 256 * 9, v1);
        }
        __syncthreads();   // mma reads of A[buf] + writes of A[buf^1] complete

        // fragments -> logits
        #pragma unroll
        for (int mt = 0; mt < 5; mt++)
            #pragma unroll
            for (int nt = 0; nt < 2; nt++) {
                int r0 = mt * 16 + (l >> 2);
                int c0 = w * 16 + nt * 8 + 2 * (l & 3);
                *(float2*)(sLog + r0 * LSTRIDE + c0) =
                    make_float2(acc[mt][nt][0], acc[mt][nt][1]);
                *(float2*)(sLog + (r0 + 8) * LSTRIDE + c0) =
                    make_float2(acc[mt][nt][2], acc[mt][nt][3]);
            }
        __syncthreads();

        // epilogue: softmax over 20 edges + gather; 2 (node,ch) per thread
        {
            const int j = tid & 127;
            #pragma unroll
            for (int h = 0; h < 2; h++) {
                const int tt = (tid >> 7) + 2 * h;
                float L[EE];
                #pragma unroll
                for (int i = 0; i < EE; i++)
                    L[i] = sLog[(tt * EE + i) * LSTRIDE + j];
                float m = L[0];
                #pragma unroll
                for (int i = 1; i < EE; i++) m = fmaxf(m, L[i]);
                float s = 0.f;
                #pragma unroll
                for (int i = 0; i < EE; i++) {
                    float ex = __expf(L[i] - m);
                    L[i] = ex;
                    s += ex;
                }
                const int node = tile * TNODES + tt;
                const int bbase = (node / NN) * NN;
                float accO = 0.f;
                #pragma unroll
                for (int i = 0; i < EE; i++) {
                    int rr = sIdx[tt * EE + i];
                    accO += L[i] * g_Vx[(size_t)(bbase + rr) * HH + j];
                }
                out[(size_t)node * HH + j] += accO * __fdividef(1.f, s);
            }
        }
        __syncthreads();
        buf ^= 1;
    }
}

// ---------------------------------------------------------------------------
extern "C" void kernel_launch(void* const* d_in, const int* in_sizes, int n_in,
                              void* d_out, int out_size)
{
    const float* x          = (const float*)d_in[0];
    const float* e          = (const float*)d_in[1];
    const float* Wu         = (const float*)d_in[2];
    const float* bu         = (const float*)d_in[3];
    const float* Wv         = (const float*)d_in[4];
    const float* bv         = (const float*)d_in[5];
    const float* We         = (const float*)d_in[6];
    const int*   edge_index = (const int*)d_in[8];
    float* out = (float*)d_out;

    int sms = 148;
    cudaDeviceGetAttribute(&sms, cudaDevAttrMultiProcessorCount, 0);

    cudaFuncSetAttribute(kA, cudaFuncAttributeMaxDynamicSharedMemorySize, KA_SMEM);
    cudaFuncSetAttribute(kB, cudaFuncAttributeMaxDynamicSharedMemorySize, SMEMB);

    kA<<<(BB * NN) / 128, 512, KA_SMEM>>>(x, Wu, bu, Wv, bv, out);
    kB<<<2 * sms, 256, SMEMB>>>(e, We, edge_index, out);
}

// round 13
// speedup vs baseline: 1.0165x; 1.0165x over previous
#include <cuda_runtime.h>
#include <cuda_fp16.h>
#include <cstdint>

#define BB 8
#define NN 2000
#define EE 20
#define HH 128
#define TNODES 4
#define TROWS 80                 // 4 nodes * 20 edges per CTA tile
#define NTILES 4000              // 16000 nodes / 4

// kB smem layout (bytes). Stage (fp32 next-tile, 40960B) and logits
// (80x132 fp32 = 42240B) ALIAS the same region: stage is drained into the
// A-buffer before logits are written each tile.
#define SA_OFF    0              // A fp16 double buffer: 2 * 20480
#define ABUF_B    20480
#define ALIAS_OFF 40960          // stage / logits shared region (42240B)
#define LSTRIDE   132
#define SIDX_OFF  83200          // 80 ints
#define SMEMB     83584
// transient W-build area (before the pipeline starts): WH at offset 0

// kA smem layout
#define KA_SX 0                  // x fp16 swizzled 32768
#define KA_WH 32768              // W hi fp16 swizzled 32768
#define KA_WL 65536              // W lo fp16 swizzled 32768
#define KA_SMEM 98304

__device__ float g_Vx[BB * NN * HH];

// ---------------------------------------------------------------- helpers
__device__ __forceinline__ uint32_t smem_u32(const void* p) {
    uint32_t a;
    asm("{ .reg .u64 t; cvta.to.shared.u64 t, %1; cvt.u32.u64 %0, t; }" : "=r"(a) : "l"(p));
    return a;
}
// pack two fp32 -> fp16x2 (first arg -> low half)
__device__ __forceinline__ uint32_t pack_f16(float lo, float hi) {
    uint32_t r;
    asm("cvt.rn.f16x2.f32 %0, %1, %2;" : "=r"(r) : "f"(hi), "f"(lo));
    return r;
}
__device__ __forceinline__ float f16lo(uint32_t p) {
    float f;
    asm("{ .reg .b16 l, h; mov.b32 {l, h}, %1; cvt.f32.f16 %0, l; }" : "=f"(f) : "r"(p));
    return f;
}
__device__ __forceinline__ float f16hi(uint32_t p) {
    float f;
    asm("{ .reg .b16 l, h; mov.b32 {l, h}, %1; cvt.f32.f16 %0, h; }" : "=f"(f) : "r"(p));
    return f;
}
__device__ __forceinline__ void ldsm4(uint32_t addr, uint32_t* r) {
    asm volatile("ldmatrix.sync.aligned.m8n8.x4.shared.b16 {%0,%1,%2,%3}, [%4];"
                 : "=r"(r[0]), "=r"(r[1]), "=r"(r[2]), "=r"(r[3]) : "r"(addr));
}
__device__ __forceinline__ void ldsm4t(uint32_t addr, uint32_t* r) {
    asm volatile("ldmatrix.sync.aligned.m8n8.x4.trans.shared.b16 {%0,%1,%2,%3}, [%4];"
                 : "=r"(r[0]), "=r"(r[1]), "=r"(r[2]), "=r"(r[3]) : "r"(addr));
}
__device__ __forceinline__ void mma16816(float* d, const uint32_t* a, uint32_t b0, uint32_t b1) {
    asm volatile("mma.sync.aligned.m16n8k16.row.col.f32.f16.f16.f32 "
                 "{%0,%1,%2,%3}, {%4,%5,%6,%7}, {%8,%9}, {%0,%1,%2,%3};"
                 : "+f"(d[0]), "+f"(d[1]), "+f"(d[2]), "+f"(d[3])
                 : "r"(a[0]), "r"(a[1]), "r"(a[2]), "r"(a[3]), "r"(b0), "r"(b1));
}
__device__ __forceinline__ void cpasync16(uint32_t saddr, const void* g) {
    asm volatile("cp.async.cg.shared.global [%0], [%1], 16;" :: "r"(saddr), "l"(g));
}

// swizzled fp16 256B-row offset for float4-chunk index ch4 of a 128-wide tile
__device__ __forceinline__ uint32_t swoff(int ch4) {
    int row = ch4 >> 5, c4 = ch4 & 31;
    return ((uint32_t)row << 8) + ((((uint32_t)(c4 >> 1)) ^ (row & 7)) << 4) + ((c4 & 1) << 3);
}
// fp32 float4 -> fp16, stored swizzled
__device__ __forceinline__ void cvtStoreF16(char* dst, int ch4, float4 v) {
    uint32_t sw = swoff(ch4);
    *(uint2*)(dst + sw) = make_uint2(pack_f16(v.x, v.y), pack_f16(v.z, v.w));
}
// fp32 float4 -> fp16 hi + residual lo, stored swizzled
__device__ __forceinline__ void cvtStoreHL(char* dh, char* dl, int ch4, float4 v) {
    uint32_t sw = swoff(ch4);
    uint32_t h0 = pack_f16(v.x, v.y);
    uint32_t h1 = pack_f16(v.z, v.w);
    uint32_t l0 = pack_f16(v.x - f16lo(h0), v.y - f16hi(h0));
    uint32_t l1 = pack_f16(v.z - f16lo(h1), v.w - f16hi(h1));
    *(uint2*)(dh + sw) = make_uint2(h0, h1);
    *(uint2*)(dl + sw) = make_uint2(l0, l1);
}

// ---------------------------------------------------------------------------
// Kernel A (tensor-core): per CTA, 128 rows of x. Two passes:
//   pass 0: out  = x @ Wu + bu
//   pass 1: g_Vx = x @ Wv + bv
// 512 threads / 16 warps. fp16 2-term W split, x in fp16.
// ---------------------------------------------------------------------------
__global__ void __launch_bounds__(512, 1) kA(
    const float* __restrict__ x, const float* __restrict__ Wu,
    const float* __restrict__ bu, const float* __restrict__ Wv,
    const float* __restrict__ bv, float* __restrict__ out)
{
    extern __shared__ __align__(1024) char smem[];
    const uint32_t sb = smem_u32(smem);
    const int tid = threadIdx.x;
    const int w = tid >> 5;
    const int l = tid & 31;
    const int mg = w >> 3;
    const int nc = w & 7;
    const int lrow = (l & 7) + ((l >> 3) & 1) * 8;
    const int lchk = l >> 4;
    const size_t rowBase = (size_t)blockIdx.x * 128;

    // load x tile -> fp16 swizzled  (128x128 = 4096 float4s, 8 per thread)
    {
        const float4* src = (const float4*)(x + rowBase * HH);
        #pragma unroll
        for (int q = 0; q < 8; q++) {
            int ch4 = tid + 512 * q;
            cvtStoreF16((char*)smem + KA_SX, ch4, src[ch4]);
        }
    }

    #pragma unroll 1
    for (int pass = 0; pass < 2; pass++) {
        const float* W = pass ? Wv : Wu;
        const float* bias = pass ? bv : bu;
        // build W hi/lo  (4096 float4s, 8 per thread)
        #pragma unroll
        for (int q = 0; q < 8; q++) {
            int ch4 = tid + 512 * q;
            cvtStoreHL((char*)smem + KA_WH, (char*)smem + KA_WL, ch4,
                       ((const float4*)W)[ch4]);
        }
        __syncthreads();

        float acc[4][2][4];
        #pragma unroll
        for (int mt = 0; mt < 4; mt++)
            #pragma unroll
            for (int nt = 0; nt < 2; nt++)
                #pragma unroll
                for (int q = 0; q < 4; q++) acc[mt][nt][q] = 0.f;

        #pragma unroll
        for (int ks = 0; ks < 8; ks++) {
            uint32_t bh[4], bl[4];
            {
                int row = ks * 16 + lrow;
                uint32_t off = ((uint32_t)row << 8) +
                               (((uint32_t)((nc * 2 + lchk) ^ (row & 7))) << 4);
                ldsm4t(sb + KA_WH + off, bh);
                ldsm4t(sb + KA_WL + off, bl);
            }
            #pragma unroll
            for (int mt = 0; mt < 4; mt++) {
                uint32_t a[4];
                int row = mg * 64 + mt * 16 + lrow;
                uint32_t off = ((uint32_t)row << 8) +
                               (((uint32_t)((ks * 2 + lchk) ^ (row & 7))) << 4);
                ldsm4(sb + KA_SX + off, a);
                mma16816(acc[mt][0], a, bh[0], bh[1]);
                mma16816(acc[mt][1], a, bh[2], bh[3]);
                mma16816(acc[mt][0], a, bl[0], bl[1]);
                mma16816(acc[mt][1], a, bl[2], bl[3]);
            }
        }

        float* dst = pass ? g_Vx : out;
        #pragma unroll
        for (int nt = 0; nt < 2; nt++) {
            int c0 = nc * 16 + nt * 8 + 2 * (l & 3);
            float2 b2 = *(const float2*)(bias + c0);
            #pragma unroll
            for (int mt = 0; mt < 4; mt++) {
                int r0 = mg * 64 + mt * 16 + (l >> 2);
                *(float2*)(dst + (rowBase + r0) * HH + c0) =
                    make_float2(acc[mt][nt][0] + b2.x, acc[mt][nt][1] + b2.y);
                *(float2*)(dst + (rowBase + r0 + 8) * HH + c0) =
                    make_float2(acc[mt][nt][2] + b2.x, acc[mt][nt][3] + b2.y);
            }
        }
        __syncthreads();   // W area reads done before next pass overwrites
    }
}

// ---------------------------------------------------------------------------
// Kernel B: logits = e16 @ We16 via fp16 mma (single W term), cp.async
// staged pipeline (R11), warp grid 4 n-groups (n32) x 2 m-groups to halve
// A-ldsm traffic. 256 threads / 8 warps, 2 CTAs/SM.
// ---------------------------------------------------------------------------
__global__ void __launch_bounds__(256, 2) kB(
    const float* __restrict__ e, const float* __restrict__ We,
    const int* __restrict__ edge_index, float* __restrict__ out)
{
    extern __shared__ __align__(1024) char smem[];
    const uint32_t sb = smem_u32(smem);
    float* sLog = (float*)(smem + ALIAS_OFF);
    int*   sIdx = (int*)(smem + SIDX_OFF);
    const int tid = threadIdx.x;
    const int w = tid >> 5;
    const int l = tid & 31;
    const int ng = w & 3;            // n-cols [32ng, 32ng+32)
    const int mg = w >> 2;           // 0: m-tiles 0..2, 1: m-tiles 3..4
    const int mts = mg ? 2 : 3;      // warp-uniform
    const int mbase = mg * 3;
    const int lrow = (l & 7) + ((l >> 3) & 1) * 8;
    const int lchk = l >> 4;

    // ---- Build We (hi only) fp16 swizzled at offset 0 (transient) ----
    #pragma unroll
    for (int q = 0; q < 16; q++) {
        int ch4 = tid + 256 * q;     // 0..4095
        cvtStoreF16((char*)smem, ch4, ((const float4*)We)[ch4]);
    }
    __syncthreads();

    // ---- Hoist W fragments: n32 per warp, all K -> 64 regs ----
    uint32_t bh[8][8];
    #pragma unroll
    for (int ks = 0; ks < 8; ks++) {
        int row = ks * 16 + lrow;
        uint32_t rbase = ((uint32_t)row << 8);
        uint32_t o0 = rbase + (((uint32_t)((ng * 4 + lchk) ^ (row & 7))) << 4);
        uint32_t o1 = rbase + (((uint32_t)((ng * 4 + 2 + lchk) ^ (row & 7))) << 4);
        ldsm4t(sb + o0, bh[ks]);
        ldsm4t(sb + o1, bh[ks] + 4);
    }
    __syncthreads();   // hoists done before region is reused

    // ---- Prologue: stage tile0 -> A[0] ----
    const int tile0 = blockIdx.x;
    if (tile0 < NTILES) {
        const char* src = (const char*)(e + (size_t)tile0 * TROWS * HH);
        #pragma unroll
        for (int q = 0; q < 10; q++) {
            int ch4 = tid + 256 * q;
            cpasync16(sb + ALIAS_OFF + ch4 * 16, src + ch4 * 16);
        }
        asm volatile("cp.async.commit_group;");
        asm volatile("cp.async.wait_group 0;" ::: "memory");
        const float4* stg = (const float4*)(smem + ALIAS_OFF);
        #pragma unroll
        for (int q = 0; q < 10; q++) {
            int ch4 = tid + 256 * q;
            cvtStoreF16((char*)smem + SA_OFF, ch4, stg[ch4]);
        }
    }
    __syncthreads();

    int buf = 0;
    for (int tile = tile0; tile < NTILES; tile += gridDim.x) {
        const int ntile = tile + gridDim.x;
        const bool havenext = ntile < NTILES;

        // 1. stage next tile (fp32) into the alias region under the mma loop
        if (havenext) {
            const char* src = (const char*)(e + (size_t)ntile * TROWS * HH);
            #pragma unroll
            for (int q = 0; q < 10; q++) {
                int ch4 = tid + 256 * q;
                cpasync16(sb + ALIAS_OFF + ch4 * 16, src + ch4 * 16);
            }
            asm volatile("cp.async.commit_group;");
        }
        if (tid < TROWS) sIdx[tid] = edge_index[(size_t)tile * TROWS + tid];

        // 2. mma mainloop: warp computes its m-group rows x n32 cols
        float acc[3][4][4];
        #pragma unroll
        for (int mt = 0; mt < 3; mt++)
            #pragma unroll
            for (int nt = 0; nt < 4; nt++)
                #pragma unroll
                for (int q = 0; q < 4; q++) acc[mt][nt][q] = 0.f;

        const uint32_t baseA = sb + SA_OFF + buf * ABUF_B;
        #pragma unroll
        for (int ks = 0; ks < 8; ks++) {
            #pragma unroll
            for (int mt = 0; mt < 3; mt++) {
                if (mt < mts) {      // warp-uniform predicate
                    uint32_t a[4];
                    int row = (mbase + mt) * 16 + lrow;
                    uint32_t off = ((uint32_t)row << 8) +
                                   (((uint32_t)((ks * 2 + lchk) ^ (row & 7))) << 4);
                    ldsm4(baseA + off, a);
                    mma16816(acc[mt][0], a, bh[ks][0], bh[ks][1]);
                    mma16816(acc[mt][1], a, bh[ks][2], bh[ks][3]);
                    mma16816(acc[mt][2], a, bh[ks][4], bh[ks][5]);
                    mma16816(acc[mt][3], a, bh[ks][6], bh[ks][7]);
                }
            }
        }

        // 3. drain stage into the other A buffer (frees the alias region)
        if (havenext) {
            asm volatile("cp.async.wait_group 0;" ::: "memory");
            char* dst = (char*)smem + SA_OFF + (buf ^ 1) * ABUF_B;
            const float4* stg = (const float4*)(smem + ALIAS_OFF);
            #pragma unroll
            for (int q = 0; q < 10; q++) {
                int ch4 = tid + 256 * q;
                cvtStoreF16(dst, ch4, stg[ch4]);
            }
        }
        __syncthreads();

        // 4. fragments -> logits (alias region, now free)
        #pragma unroll
        for (int mt = 0; mt < 3; mt++) {
            if (mt < mts) {
                int r0 = (mbase + mt) * 16 + (l >> 2);
                #pragma unroll
                for (int nt = 0; nt < 4; nt++) {
                    int c0 = ng * 32 + nt * 8 + 2 * (l & 3);
                    *(float2*)(sLog + r0 * LSTRIDE + c0) =
                        make_float2(acc[mt][nt][0], acc[mt][nt][1]);
                    *(float2*)(sLog + (r0 + 8) * LSTRIDE + c0) =
                        make_float2(acc[mt][nt][2], acc[mt][nt][3]);
                }
            }
        }
        __syncthreads();

        // 5. epilogue: softmax over 20 edges + gather; 2 (node,ch) per thread
        {
            const int j = tid & 127;
            #pragma unroll
            for (int h = 0; h < 2; h++) {
                const int tt = (tid >> 7) + 2 * h;
                float L[EE];
                #pragma unroll
                for (int i = 0; i < EE; i++)
                    L[i] = sLog[(tt * EE + i) * LSTRIDE + j];
                float m = L[0];
                #pragma unroll
                for (int i = 1; i < EE; i++) m = fmaxf(m, L[i]);
                float s = 0.f;
                #pragma unroll
                for (int i = 0; i < EE; i++) {
                    float ex = __expf(L[i] - m);
                    L[i] = ex;
                    s += ex;
                }
                const int node = tile * TNODES + tt;
                const int bbase = (node / NN) * NN;
                float accO = 0.f;
                #pragma unroll
                for (int i = 0; i < EE; i++) {
                    int rr = sIdx[tt * EE + i];
                    accO += L[i] * g_Vx[(size_t)(bbase + rr) * HH + j];
                }
                out[(size_t)node * HH + j] += accO * __fdividef(1.f, s);
            }
        }
        __syncthreads();
        buf ^= 1;
    }
}

// ---------------------------------------------------------------------------
extern "C" void kernel_launch(void* const* d_in, const int* in_sizes, int n_in,
                              void* d_out, int out_size)
{
    const float* x          = (const float*)d_in[0];
    const float* e          = (const float*)d_in[1];
    const float* Wu         = (const float*)d_in[2];
    const float* bu         = (const float*)d_in[3];
    const float* Wv         = (const float*)d_in[4];
    const float* bv         = (const float*)d_in[5];
    const float* We         = (const float*)d_in[6];
    const int*   edge_index = (const int*)d_in[8];
    float* out = (float*)d_out;

    int sms = 148;
    cudaDeviceGetAttribute(&sms, cudaDevAttrMultiProcessorCount, 0);

    cudaFuncSetAttribute(kA, cudaFuncAttributeMaxDynamicSharedMemorySize, KA_SMEM);
    cudaFuncSetAttribute(kB, cudaFuncAttributeMaxDynamicSharedMemorySize, SMEMB);

    kA<<<(BB * NN) / 128, 512, KA_SMEM>>>(x, Wu, bu, Wv, bv, out);
    kB<<<2 * sms, 256, SMEMB>>>(e, We, edge_index, out);
}

// round 15
// speedup vs baseline: 1.0201x; 1.0035x over previous
#include <cuda_runtime.h>
#include <cuda_fp16.h>
#include <cstdint>

#define BB 8
#define NN 2000
#define EE 20
#define HH 128
#define TNODES 4
#define TROWS 80                 // 4 nodes * 20 edges per CTA tile
#define NTILES 4000              // 16000 nodes / 4

// kB smem layout (bytes). Stage (fp32 next-tile, 40960B) and logits
// (80x132 fp32 = 42240B) ALIAS the same region.
#define SA_OFF    0              // A fp16 double buffer: 2 * 20480
#define ABUF_B    20480
#define ALIAS_OFF 40960          // stage / logits shared region (42240B)
#define LSTRIDE   132
#define SIDX_OFF  83200          // 80 ints
#define SMEMB     83584

// kA smem layout (64-row x tile)
#define KA_SX 0                  // x fp16 swizzled 16384
#define KA_WH 16384              // W hi fp16 swizzled 32768
#define KA_WL 49152              // W lo fp16 swizzled 32768
#define KA_SMEM 81920

__device__ float g_Vx[BB * NN * HH];
// Prebuilt fp16 weights (linear chunk order; uint2 = 4 fp16)
__device__ uint2 gWuh[4096], gWul[4096], gWvh[4096], gWvl[4096], gWeh[4096];

// ---------------------------------------------------------------- helpers
__device__ __forceinline__ uint32_t smem_u32(const void* p) {
    uint32_t a;
    asm("{ .reg .u64 t; cvta.to.shared.u64 t, %1; cvt.u32.u64 %0, t; }" : "=r"(a) : "l"(p));
    return a;
}
__device__ __forceinline__ uint32_t pack_f16(float lo, float hi) {
    uint32_t r;
    asm("cvt.rn.f16x2.f32 %0, %1, %2;" : "=r"(r) : "f"(hi), "f"(lo));
    return r;
}
__device__ __forceinline__ float f16lo(uint32_t p) {
    float f;
    asm("{ .reg .b16 l, h; mov.b32 {l, h}, %1; cvt.f32.f16 %0, l; }" : "=f"(f) : "r"(p));
    return f;
}
__device__ __forceinline__ float f16hi(uint32_t p) {
    float f;
    asm("{ .reg .b16 l, h; mov.b32 {l, h}, %1; cvt.f32.f16 %0, h; }" : "=f"(f) : "r"(p));
    return f;
}
__device__ __forceinline__ void ldsm4(uint32_t addr, uint32_t* r) {
    asm volatile("ldmatrix.sync.aligned.m8n8.x4.shared.b16 {%0,%1,%2,%3}, [%4];"
                 : "=r"(r[0]), "=r"(r[1]), "=r"(r[2]), "=r"(r[3]) : "r"(addr));
}
__device__ __forceinline__ void ldsm4t(uint32_t addr, uint32_t* r) {
    asm volatile("ldmatrix.sync.aligned.m8n8.x4.trans.shared.b16 {%0,%1,%2,%3}, [%4];"
                 : "=r"(r[0]), "=r"(r[1]), "=r"(r[2]), "=r"(r[3]) : "r"(addr));
}
__device__ __forceinline__ void mma16816(float* d, const uint32_t* a, uint32_t b0, uint32_t b1) {
    asm volatile("mma.sync.aligned.m16n8k16.row.col.f32.f16.f16.f32 "
                 "{%0,%1,%2,%3}, {%4,%5,%6,%7}, {%8,%9}, {%0,%1,%2,%3};"
                 : "+f"(d[0]), "+f"(d[1]), "+f"(d[2]), "+f"(d[3])
                 : "r"(a[0]), "r"(a[1]), "r"(a[2]), "r"(a[3]), "r"(b0), "r"(b1));
}
__device__ __forceinline__ void cpasync16(uint32_t saddr, const void* g) {
    asm volatile("cp.async.cg.shared.global [%0], [%1], 16;" :: "r"(saddr), "l"(g));
}

// swizzled fp16 256B-row offset for float4-chunk index ch4 of a 128-wide tile
__device__ __forceinline__ uint32_t swoff(int ch4) {
    int row = ch4 >> 5, c4 = ch4 & 31;
    return ((uint32_t)row << 8) + ((((uint32_t)(c4 >> 1)) ^ (row & 7)) << 4) + ((c4 & 1) << 3);
}
// fp32 float4 -> fp16, stored swizzled
__device__ __forceinline__ void cvtStoreF16(char* dst, int ch4, float4 v) {
    uint32_t sw = swoff(ch4);
    *(uint2*)(dst + sw) = make_uint2(pack_f16(v.x, v.y), pack_f16(v.z, v.w));
}

// ---------------------------------------------------------------------------
// Kernel W: one-time fp32 -> fp16 (hi [, lo residual]) weight conversion.
// grid 3: CTA 0 = Wu (hi+lo), CTA 1 = Wv (hi+lo), CTA 2 = We (hi only).
// ---------------------------------------------------------------------------
__global__ void __launch_bounds__(256, 1) kW(
    const float* __restrict__ Wu, const float* __restrict__ Wv,
    const float* __restrict__ We)
{
    const int c = blockIdx.x;
    const int tid = threadIdx.x;
    const float4* src = (const float4*)(c == 0 ? Wu : (c == 1 ? Wv : We));
    uint2* dh = (c == 0) ? gWuh : (c == 1 ? gWvh : gWeh);
    uint2* dl = (c == 0) ? gWul : gWvl;       // unused for c==2
    #pragma unroll
    for (int q = 0; q < 16; q++) {
        int ch4 = tid + 256 * q;              // 0..4095
        float4 v = src[ch4];
        uint32_t h0 = pack_f16(v.x, v.y);
        uint32_t h1 = pack_f16(v.z, v.w);
        dh[ch4] = make_uint2(h0, h1);
        if (c < 2) {
            uint32_t l0 = pack_f16(v.x - f16lo(h0), v.y - f16hi(h0));
            uint32_t l1 = pack_f16(v.z - f16lo(h1), v.w - f16hi(h1));
            dl[ch4] = make_uint2(l0, l1);
        }
    }
}

// ---------------------------------------------------------------------------
// Kernel A (tensor-core): per CTA, 64 rows of x (grid 250). Two passes:
//   pass 0: out  = x @ Wu + bu     pass 1: g_Vx = x @ Wv + bv
// fp16 2-term W split; W loaded prebuilt fp16 from kW (no per-CTA cvt).
// 512 threads / 16 warps: mg = w>>3 owns m-tiles {2mg, 2mg+1}; nc = w&7 n16.
// ---------------------------------------------------------------------------
__global__ void __launch_bounds__(512, 1) kA(
    const float* __restrict__ x, const float* __restrict__ bu,
    const float* __restrict__ bv, float* __restrict__ out)
{
    extern __shared__ __align__(1024) char smem[];
    const uint32_t sb = smem_u32(smem);
    const int tid = threadIdx.x;
    const int w = tid >> 5;
    const int l = tid & 31;
    const int mg = w >> 3;
    const int nc = w & 7;
    const int lrow = (l & 7) + ((l >> 3) & 1) * 8;
    const int lchk = l >> 4;
    const size_t rowBase = (size_t)blockIdx.x * 64;

    // load x tile -> fp16 swizzled (64x128 = 2048 float4s, 4 per thread)
    {
        const float4* src = (const float4*)(x + rowBase * HH);
        #pragma unroll
        for (int q = 0; q < 4; q++) {
            int ch4 = tid + 512 * q;
            cvtStoreF16((char*)smem + KA_SX, ch4, src[ch4]);
        }
    }

    #pragma unroll 1
    for (int pass = 0; pass < 2; pass++) {
        const uint2* Gh = pass ? gWvh : gWuh;
        const uint2* Gl = pass ? gWvl : gWul;
        const float* bias = pass ? bv : bu;
        // build W hi/lo from prebuilt fp16 (4096 uint2, 8 per thread)
        #pragma unroll
        for (int q = 0; q < 8; q++) {
            int ch4 = tid + 512 * q;
            uint32_t sw = swoff(ch4);
            *(uint2*)(smem + KA_WH + sw) = Gh[ch4];
            *(uint2*)(smem + KA_WL + sw) = Gl[ch4];
        }
        __syncthreads();

        float acc[2][2][4];
        #pragma unroll
        for (int mt = 0; mt < 2; mt++)
            #pragma unroll
            for (int nt = 0; nt < 2; nt++)
                #pragma unroll
                for (int q = 0; q < 4; q++) acc[mt][nt][q] = 0.f;

        #pragma unroll
        for (int ks = 0; ks < 8; ks++) {
            uint32_t bh[4], bl[4];
            {
                int row = ks * 16 + lrow;
                uint32_t off = ((uint32_t)row << 8) +
                               (((uint32_t)((nc * 2 + lchk) ^ (row & 7))) << 4);
                ldsm4t(sb + KA_WH + off, bh);
                ldsm4t(sb + KA_WL + off, bl);
            }
            #pragma unroll
            for (int mt = 0; mt < 2; mt++) {
                uint32_t a[4];
                int row = mg * 32 + mt * 16 + lrow;
                uint32_t off = ((uint32_t)row << 8) +
                               (((uint32_t)((ks * 2 + lchk) ^ (row & 7))) << 4);
                ldsm4(sb + KA_SX + off, a);
                mma16816(acc[mt][0], a, bh[0], bh[1]);
                mma16816(acc[mt][1], a, bh[2], bh[3]);
                mma16816(acc[mt][0], a, bl[0], bl[1]);
                mma16816(acc[mt][1], a, bl[2], bl[3]);
            }
        }

        float* dst = pass ? g_Vx : out;
        #pragma unroll
        for (int nt = 0; nt < 2; nt++) {
            int c0 = nc * 16 + nt * 8 + 2 * (l & 3);
            float2 b2 = *(const float2*)(bias + c0);
            #pragma unroll
            for (int mt = 0; mt < 2; mt++) {
                int r0 = mg * 32 + mt * 16 + (l >> 2);
                *(float2*)(dst + (rowBase + r0) * HH + c0) =
                    make_float2(acc[mt][nt][0] + b2.x, acc[mt][nt][1] + b2.y);
                *(float2*)(dst + (rowBase + r0 + 8) * HH + c0) =
                    make_float2(acc[mt][nt][2] + b2.x, acc[mt][nt][3] + b2.y);
            }
        }
        __syncthreads();   // W area reads done before next pass overwrites
    }
}

// ---------------------------------------------------------------------------
// Kernel B: logits = e16 @ We16 via fp16 mma (single W term), cp.async staged
// pipeline. EXACT R11 structure (best known: 70.2us). 256 threads / 8 warps,
// 2 CTAs/SM. Warp w owns n-cols [16w,16w+16), all 5 m-tiles. W in registers.
// Only change vs R11: We build loads prebuilt fp16 from kW.
// ---------------------------------------------------------------------------
__global__ void __launch_bounds__(256, 2) kB(
    const float* __restrict__ e, const int* __restrict__ edge_index,
    float* __restrict__ out)
{
    extern __shared__ __align__(1024) char smem[];
    const uint32_t sb = smem_u32(smem);
    float* sLog = (float*)(smem + ALIAS_OFF);
    int*   sIdx = (int*)(smem + SIDX_OFF);
    const int tid = threadIdx.x;
    const int w = tid >> 5;
    const int l = tid & 31;
    const int lrow = (l & 7) + ((l >> 3) & 1) * 8;
    const int lchk = l >> 4;

    // ---- Build We (hi) fp16 swizzled at offset 0 from prebuilt (transient) --
    #pragma unroll
    for (int q = 0; q < 16; q++) {
        int ch4 = tid + 256 * q;     // 0..4095
        *(uint2*)(smem + swoff(ch4)) = gWeh[ch4];
    }
    __syncthreads();

    // ---- Hoist W fragments (n16 per warp, all K): 32 regs ----
    uint32_t bh[8][4];
    #pragma unroll
    for (int ks = 0; ks < 8; ks++) {
        int row = ks * 16 + lrow;
        uint32_t off = ((uint32_t)row << 8) +
                       (((uint32_t)((w * 2 + lchk) ^ (row & 7))) << 4);
        ldsm4t(sb + off, bh[ks]);
    }
    __syncthreads();   // hoists done before region is reused

    // ---- Prologue: stage tile0 -> A[0] ----
    const int tile0 = blockIdx.x;
    if (tile0 < NTILES) {
        const char* src = (const char*)(e + (size_t)tile0 * TROWS * HH);
        #pragma unroll
        for (int q = 0; q < 10; q++) {
            int ch4 = tid + 256 * q;
            cpasync16(sb + ALIAS_OFF + ch4 * 16, src + ch4 * 16);
        }
        asm volatile("cp.async.commit_group;");
        asm volatile("cp.async.wait_group 0;" ::: "memory");
        const float4* stg = (const float4*)(smem + ALIAS_OFF);
        #pragma unroll
        for (int q = 0; q < 10; q++) {
            int ch4 = tid + 256 * q;
            cvtStoreF16((char*)smem + SA_OFF, ch4, stg[ch4]);
        }
    }
    __syncthreads();

    int buf = 0;
    for (int tile = tile0; tile < NTILES; tile += gridDim.x) {
        const int ntile = tile + gridDim.x;
        const bool havenext = ntile < NTILES;

        // 1. stage next tile (fp32) into the alias region under the mma loop
        if (havenext) {
            const char* src = (const char*)(e + (size_t)ntile * TROWS * HH);
            #pragma unroll
            for (int q = 0; q < 10; q++) {
                int ch4 = tid + 256 * q;
                cpasync16(sb + ALIAS_OFF + ch4 * 16, src + ch4 * 16);
            }
            asm volatile("cp.async.commit_group;");
        }
        if (tid < TROWS) sIdx[tid] = edge_index[(size_t)tile * TROWS + tid];

        // 2. mma mainloop: D[80 x 128], 5 m-tiles per warp, single W term
        float acc[5][2][4];
        #pragma unroll
        for (int mt = 0; mt < 5; mt++)
            #pragma unroll
            for (int nt = 0; nt < 2; nt++)
                #pragma unroll
                for (int q = 0; q < 4; q++) acc[mt][nt][q] = 0.f;

        const uint32_t baseA = sb + SA_OFF + buf * ABUF_B;
        #pragma unroll
        for (int ks = 0; ks < 8; ks++) {
            #pragma unroll
            for (int mt = 0; mt < 5; mt++) {
                uint32_t a[4];
                int row = mt * 16 + lrow;
                uint32_t off = ((uint32_t)row << 8) +
                               (((uint32_t)((ks * 2 + lchk) ^ (row & 7))) << 4);
                ldsm4(baseA + off, a);
                mma16816(acc[mt][0], a, bh[ks][0], bh[ks][1]);
                mma16816(acc[mt][1], a, bh[ks][2], bh[ks][3]);
            }
        }

        // 3. drain stage into the other A buffer (frees the alias region)
        if (havenext) {
            asm volatile("cp.async.wait_group 0;" ::: "memory");
            char* dst = (char*)smem + SA_OFF + (buf ^ 1) * ABUF_B;
            const float4* stg = (const float4*)(smem + ALIAS_OFF);
            #pragma unroll
            for (int q = 0; q < 10; q++) {
                int ch4 = tid + 256 * q;
                cvtStoreF16(dst, ch4, stg[ch4]);
            }
        }
        __syncthreads();

        // 4. fragments -> logits (alias region, now free)
        #pragma unroll
        for (int mt = 0; mt < 5; mt++)
            #pragma unroll
            for (int nt = 0; nt < 2; nt++) {
                int r0 = mt * 16 + (l >> 2);
                int c0 = w * 16 + nt * 8 + 2 * (l & 3);
                *(float2*)(sLog + r0 * LSTRIDE + c0) =
                    make_float2(acc[mt][nt][0], acc[mt][nt][1]);
                *(float2*)(sLog + (r0 + 8) * LSTRIDE + c0) =
                    make_float2(acc[mt][nt][2], acc[mt][nt][3]);
            }
        __syncthreads();

        // 5. epilogue: softmax over 20 edges + gather; 2 (node,ch) per thread
        {
            const int j = tid & 127;
            #pragma unroll
            for (int h = 0; h < 2; h++) {
                const int tt = (tid >> 7) + 2 * h;
                float L[EE];
                #pragma unroll
                for (int i = 0; i < EE; i++)
                    L[i] = sLog[(tt * EE + i) * LSTRIDE + j];
                float m = L[0];
                #pragma unroll
                for (int i = 1; i < EE; i++) m = fmaxf(m, L[i]);
                float s = 0.f;
                #pragma unroll
                for (int i = 0; i < EE; i++) {
                    float ex = __expf(L[i] - m);
                    L[i] = ex;
                    s += ex;
                }
                const int node = tile * TNODES + tt;
                const int bbase = (node / NN) * NN;
                float accO = 0.f;
                #pragma unroll
                for (int i = 0; i < EE; i++) {
                    int rr = sIdx[tt * EE + i];
                    accO += L[i] * g_Vx[(size_t)(bbase + rr) * HH + j];
                }
                out[(size_t)node * HH + j] += accO * __fdividef(1.f, s);
            }
        }
        __syncthreads();
        buf ^= 1;
    }
}

// ---------------------------------------------------------------------------
extern "C" void kernel_launch(void* const* d_in, const int* in_sizes, int n_in,
                              void* d_out, int out_size)
{
    const float* x          = (const float*)d_in[0];
    const float* e          = (const float*)d_in[1];
    const float* Wu         = (const float*)d_in[2];
    const float* bu         = (const float*)d_in[3];
    const float* Wv         = (const float*)d_in[4];
    const float* bv         = (const float*)d_in[5];
    const float* We         = (const float*)d_in[6];
    const int*   edge_index = (const int*)d_in[8];
    float* out = (float*)d_out;

    int sms = 148;
    cudaDeviceGetAttribute(&sms, cudaDevAttrMultiProcessorCount, 0);

    cudaFuncSetAttribute(kA, cudaFuncAttributeMaxDynamicSharedMemorySize, KA_SMEM);
    cudaFuncSetAttribute(kB, cudaFuncAttributeMaxDynamicSharedMemorySize, SMEMB);

    kW<<<3, 256>>>(Wu, Wv, We);
    kA<<<(BB * NN) / 64, 512, KA_SMEM>>>(x, bu, bv, out);
    kB<<<2 * sms, 256, SMEMB>>>(e, edge_index, out);
}

// round 16
// speedup vs baseline: 1.1488x; 1.1261x over previous
#include <cuda_runtime.h>
#include <cuda_fp16.h>
#include <cstdint>

#define BB 8
#define NN 2000
#define EE 20
#define HH 128
#define TNODES 4
#define TROWS 80                 // 4 nodes * 20 edges per CTA tile
#define NTILES 4000              // 16000 nodes / 4

// kB smem layout (bytes). Stage (fp32 next-tile, 40960B) and logits
// (80x132 fp32 = 42240B) ALIAS the same region.
#define SA_OFF    0              // A fp16 double buffer: 2 * 20480
#define ABUF_B    20480
#define ALIAS_OFF 40960          // stage / logits shared region (42240B)
#define LSTRIDE   132
#define SIDX_OFF  83200          // 80 ints
#define SMEMB     83584

// kA smem layout (128-row x tile, single-term weights, fused U+V)
#define KA_SX 0                  // x fp16 swizzled 32768
#define KA_WU 32768              // Wu hi fp16 swizzled 32768
#define KA_WV 65536              // Wv hi fp16 swizzled 32768
#define KA_SMEM 98304

__device__ float g_Vx[BB * NN * HH];

// ---------------------------------------------------------------- helpers
__device__ __forceinline__ uint32_t smem_u32(const void* p) {
    uint32_t a;
    asm("{ .reg .u64 t; cvta.to.shared.u64 t, %1; cvt.u32.u64 %0, t; }" : "=r"(a) : "l"(p));
    return a;
}
__device__ __forceinline__ uint32_t pack_f16(float lo, float hi) {
    uint32_t r;
    asm("cvt.rn.f16x2.f32 %0, %1, %2;" : "=r"(r) : "f"(hi), "f"(lo));
    return r;
}
__device__ __forceinline__ void ldsm4(uint32_t addr, uint32_t* r) {
    asm volatile("ldmatrix.sync.aligned.m8n8.x4.shared.b16 {%0,%1,%2,%3}, [%4];"
                 : "=r"(r[0]), "=r"(r[1]), "=r"(r[2]), "=r"(r[3]) : "r"(addr));
}
__device__ __forceinline__ void ldsm4t(uint32_t addr, uint32_t* r) {
    asm volatile("ldmatrix.sync.aligned.m8n8.x4.trans.shared.b16 {%0,%1,%2,%3}, [%4];"
                 : "=r"(r[0]), "=r"(r[1]), "=r"(r[2]), "=r"(r[3]) : "r"(addr));
}
__device__ __forceinline__ void mma16816(float* d, const uint32_t* a, uint32_t b0, uint32_t b1) {
    asm volatile("mma.sync.aligned.m16n8k16.row.col.f32.f16.f16.f32 "
                 "{%0,%1,%2,%3}, {%4,%5,%6,%7}, {%8,%9}, {%0,%1,%2,%3};"
                 : "+f"(d[0]), "+f"(d[1]), "+f"(d[2]), "+f"(d[3])
                 : "r"(a[0]), "r"(a[1]), "r"(a[2]), "r"(a[3]), "r"(b0), "r"(b1));
}
__device__ __forceinline__ void cpasync16(uint32_t saddr, const void* g) {
    asm volatile("cp.async.cg.shared.global [%0], [%1], 16;" :: "r"(saddr), "l"(g));
}

// swizzled fp16 256B-row offset for float4-chunk index ch4 of a 128-wide tile
__device__ __forceinline__ uint32_t swoff(int ch4) {
    int row = ch4 >> 5, c4 = ch4 & 31;
    return ((uint32_t)row << 8) + ((((uint32_t)(c4 >> 1)) ^ (row & 7)) << 4) + ((c4 & 1) << 3);
}
// fp32 float4 -> fp16, stored swizzled
__device__ __forceinline__ void cvtStoreF16(char* dst, int ch4, float4 v) {
    uint32_t sw = swoff(ch4);
    *(uint2*)(dst + sw) = make_uint2(pack_f16(v.x, v.y), pack_f16(v.z, v.w));
}

// ---------------------------------------------------------------------------
// Kernel A (tensor-core): per CTA, 128 rows of x (grid 125, 1 wave), SINGLE
// fused pass: out = x@Wu + bu AND g_Vx = x@Wv + bv off shared A-fragments.
// Single-term fp16 weights (error budget: adds ~2e-4, total ~3e-4 < 1e-3).
// 512 threads / 16 warps: mg = w>>3 owns m-tiles [4mg,4mg+4); nc = w&7 n16.
// ---------------------------------------------------------------------------
__global__ void __launch_bounds__(512, 1) kA(
    const float* __restrict__ x, const float* __restrict__ Wu,
    const float* __restrict__ bu, const float* __restrict__ Wv,
    const float* __restrict__ bv, float* __restrict__ out)
{
    extern __shared__ __align__(1024) char smem[];
    const uint32_t sb = smem_u32(smem);
    const int tid = threadIdx.x;
    const int w = tid >> 5;
    const int l = tid & 31;
    const int mg = w >> 3;
    const int nc = w & 7;
    const int lrow = (l & 7) + ((l >> 3) & 1) * 8;
    const int lchk = l >> 4;
    const size_t rowBase = (size_t)blockIdx.x * 128;

    // build x (fp16), Wu-hi, Wv-hi swizzled: 3 x 4096 float4s, 8/thread each
    {
        const float4* sx = (const float4*)(x + rowBase * HH);
        const float4* su = (const float4*)Wu;
        const float4* sv = (const float4*)Wv;
        #pragma unroll
        for (int q = 0; q < 8; q++) {
            int ch4 = tid + 512 * q;
            cvtStoreF16((char*)smem + KA_SX, ch4, sx[ch4]);
            cvtStoreF16((char*)smem + KA_WU, ch4, su[ch4]);
            cvtStoreF16((char*)smem + KA_WV, ch4, sv[ch4]);
        }
    }
    __syncthreads();

    float accU[4][2][4], accV[4][2][4];
    #pragma unroll
    for (int mt = 0; mt < 4; mt++)
        #pragma unroll
        for (int nt = 0; nt < 2; nt++)
            #pragma unroll
            for (int q = 0; q < 4; q++) { accU[mt][nt][q] = 0.f; accV[mt][nt][q] = 0.f; }

    #pragma unroll
    for (int ks = 0; ks < 8; ks++) {
        uint32_t bu4[4], bv4[4];
        {
            int row = ks * 16 + lrow;
            uint32_t off = ((uint32_t)row << 8) +
                           (((uint32_t)((nc * 2 + lchk) ^ (row & 7))) << 4);
            ldsm4t(sb + KA_WU + off, bu4);
            ldsm4t(sb + KA_WV + off, bv4);
        }
        #pragma unroll
        for (int mt = 0; mt < 4; mt++) {
            uint32_t a[4];
            int row = mg * 64 + mt * 16 + lrow;
            uint32_t off = ((uint32_t)row << 8) +
                           (((uint32_t)((ks * 2 + lchk) ^ (row & 7))) << 4);
            ldsm4(sb + KA_SX + off, a);
            mma16816(accU[mt][0], a, bu4[0], bu4[1]);
            mma16816(accU[mt][1], a, bu4[2], bu4[3]);
            mma16816(accV[mt][0], a, bv4[0], bv4[1]);
            mma16816(accV[mt][1], a, bv4[2], bv4[3]);
        }
    }

    #pragma unroll
    for (int nt = 0; nt < 2; nt++) {
        int c0 = nc * 16 + nt * 8 + 2 * (l & 3);
        float2 b2u = *(const float2*)(bu + c0);
        float2 b2v = *(const float2*)(bv + c0);
        #pragma unroll
        for (int mt = 0; mt < 4; mt++) {
            int r0 = mg * 64 + mt * 16 + (l >> 2);
            *(float2*)(out + (rowBase + r0) * HH + c0) =
                make_float2(accU[mt][nt][0] + b2u.x, accU[mt][nt][1] + b2u.y);
            *(float2*)(out + (rowBase + r0 + 8) * HH + c0) =
                make_float2(accU[mt][nt][2] + b2u.x, accU[mt][nt][3] + b2u.y);
            *(float2*)(g_Vx + (rowBase + r0) * HH + c0) =
                make_float2(accV[mt][nt][0] + b2v.x, accV[mt][nt][1] + b2v.y);
            *(float2*)(g_Vx + (rowBase + r0 + 8) * HH + c0) =
                make_float2(accV[mt][nt][2] + b2v.x, accV[mt][nt][3] + b2v.y);
        }
    }
}

// ---------------------------------------------------------------------------
// Kernel B: logits = e16 @ We16 via fp16 mma (single W term), cp.async staged
// pipeline. EXACT R11 structure (best known: 70.2us). 256 threads / 8 warps,
// 2 CTAs/SM. Warp w owns n-cols [16w,16w+16), all 5 m-tiles. W in registers.
// ---------------------------------------------------------------------------
__global__ void __launch_bounds__(256, 2) kB(
    const float* __restrict__ e, const float* __restrict__ We,
    const int* __restrict__ edge_index, float* __restrict__ out)
{
    extern __shared__ __align__(1024) char smem[];
    const uint32_t sb = smem_u32(smem);
    float* sLog = (float*)(smem + ALIAS_OFF);
    int*   sIdx = (int*)(smem + SIDX_OFF);
    const int tid = threadIdx.x;
    const int w = tid >> 5;
    const int l = tid & 31;
    const int lrow = (l & 7) + ((l >> 3) & 1) * 8;
    const int lchk = l >> 4;

    // ---- Build We (hi only) fp16 swizzled at offset 0 (transient) ----
    #pragma unroll
    for (int q = 0; q < 16; q++) {
        int ch4 = tid + 256 * q;     // 0..4095
        cvtStoreF16((char*)smem, ch4, ((const float4*)We)[ch4]);
    }
    __syncthreads();

    // ---- Hoist W fragments (n16 per warp, all K): 32 regs ----
    uint32_t bh[8][4];
    #pragma unroll
    for (int ks = 0; ks < 8; ks++) {
        int row = ks * 16 + lrow;
        uint32_t off = ((uint32_t)row << 8) +
                       (((uint32_t)((w * 2 + lchk) ^ (row & 7))) << 4);
        ldsm4t(sb + off, bh[ks]);
    }
    __syncthreads();   // hoists done before region is reused

    // ---- Prologue: stage tile0 -> A[0] ----
    const int tile0 = blockIdx.x;
    if (tile0 < NTILES) {
        const char* src = (const char*)(e + (size_t)tile0 * TROWS * HH);
        #pragma unroll
        for (int q = 0; q < 10; q++) {
            int ch4 = tid + 256 * q;
            cpasync16(sb + ALIAS_OFF + ch4 * 16, src + ch4 * 16);
        }
        asm volatile("cp.async.commit_group;");
        asm volatile("cp.async.wait_group 0;" ::: "memory");
        const float4* stg = (const float4*)(smem + ALIAS_OFF);
        #pragma unroll
        for (int q = 0; q < 10; q++) {
            int ch4 = tid + 256 * q;
            cvtStoreF16((char*)smem + SA_OFF, ch4, stg[ch4]);
        }
    }
    __syncthreads();

    int buf = 0;
    for (int tile = tile0; tile < NTILES; tile += gridDim.x) {
        const int ntile = tile + gridDim.x;
        const bool havenext = ntile < NTILES;

        // 1. stage next tile (fp32) into the alias region under the mma loop
        if (havenext) {
            const char* src = (const char*)(e + (size_t)ntile * TROWS * HH);
            #pragma unroll
            for (int q = 0; q < 10; q++) {
                int ch4 = tid + 256 * q;
                cpasync16(sb + ALIAS_OFF + ch4 * 16, src + ch4 * 16);
            }
            asm volatile("cp.async.commit_group;");
        }
        if (tid < TROWS) sIdx[tid] = edge_index[(size_t)tile * TROWS + tid];

        // 2. mma mainloop: D[80 x 128], 5 m-tiles per warp, single W term
        float acc[5][2][4];
        #pragma unroll
        for (int mt = 0; mt < 5; mt++)
            #pragma unroll
            for (int nt = 0; nt < 2; nt++)
                #pragma unroll
                for (int q = 0; q < 4; q++) acc[mt][nt][q] = 0.f;

        const uint32_t baseA = sb + SA_OFF + buf * ABUF_B;
        #pragma unroll
        for (int ks = 0; ks < 8; ks++) {
            #pragma unroll
            for (int mt = 0; mt < 5; mt++) {
                uint32_t a[4];
                int row = mt * 16 + lrow;
                uint32_t off = ((uint32_t)row << 8) +
                               (((uint32_t)((ks * 2 + lchk) ^ (row & 7))) << 4);
                ldsm4(baseA + off, a);
                mma16816(acc[mt][0], a, bh[ks][0], bh[ks][1]);
                mma16816(acc[mt][1], a, bh[ks][2], bh[ks][3]);
            }
        }

        // 3. drain stage into the other A buffer (frees the alias region)
        if (havenext) {
            asm volatile("cp.async.wait_group 0;" ::: "memory");
            char* dst = (char*)smem + SA_OFF + (buf ^ 1) * ABUF_B;
            const float4* stg = (const float4*)(smem + ALIAS_OFF);
            #pragma unroll
            for (int q = 0; q < 10; q++) {
                int ch4 = tid + 256 * q;
                cvtStoreF16(dst, ch4, stg[ch4]);
            }
        }
        __syncthreads();

        // 4. fragments -> logits (alias region, now free)
        #pragma unroll
        for (int mt = 0; mt < 5; mt++)
            #pragma unroll
            for (int nt = 0; nt < 2; nt++) {
                int r0 = mt * 16 + (l >> 2);
                int c0 = w * 16 + nt * 8 + 2 * (l & 3);
                *(float2*)(sLog + r0 * LSTRIDE + c0) =
                    make_float2(acc[mt][nt][0], acc[mt][nt][1]);
                *(float2*)(sLog + (r0 + 8) * LSTRIDE + c0) =
                    make_float2(acc[mt][nt][2], acc[mt][nt][3]);
            }
        __syncthreads();

        // 5. epilogue: softmax over 20 edges + gather; 2 (node,ch) per thread
        {
            const int j = tid & 127;
            #pragma unroll
            for (int h = 0; h < 2; h++) {
                const int tt = (tid >> 7) + 2 * h;
                float L[EE];
                #pragma unroll
                for (int i = 0; i < EE; i++)
                    L[i] = sLog[(tt * EE + i) * LSTRIDE + j];
                float m = L[0];
                #pragma unroll
                for (int i = 1; i < EE; i++) m = fmaxf(m, L[i]);
                float s = 0.f;
                #pragma unroll
                for (int i = 0; i < EE; i++) {
                    float ex = __expf(L[i] - m);
                    L[i] = ex;
                    s += ex;
                }
                const int node = tile * TNODES + tt;
                const int bbase = (node / NN) * NN;
                float accO = 0.f;
                #pragma unroll
                for (int i = 0; i < EE; i++) {
                    int rr = sIdx[tt * EE + i];
                    accO += L[i] * g_Vx[(size_t)(bbase + rr) * HH + j];
                }
                out[(size_t)node * HH + j] += accO * __fdividef(1.f, s);
            }
        }
        __syncthreads();
        buf ^= 1;
    }
}

// ---------------------------------------------------------------------------
extern "C" void kernel_launch(void* const* d_in, const int* in_sizes, int n_in,
                              void* d_out, int out_size)
{
    const float* x          = (const float*)d_in[0];
    const float* e          = (const float*)d_in[1];
    const float* Wu         = (const float*)d_in[2];
    const float* bu         = (const float*)d_in[3];
    const float* Wv         = (const float*)d_in[4];
    const float* bv         = (const float*)d_in[5];
    const float* We         = (const float*)d_in[6];
    const int*   edge_index = (const int*)d_in[8];
    float* out = (float*)d_out;

    int sms = 148;
    cudaDeviceGetAttribute(&sms, cudaDevAttrMultiProcessorCount, 0);

    cudaFuncSetAttribute(kA, cudaFuncAttributeMaxDynamicSharedMemorySize, KA_SMEM);
    cudaFuncSetAttribute(kB, cudaFuncAttributeMaxDynamicSharedMemorySize, SMEMB);

    kA<<<(BB * NN) / 128, 512, KA_SMEM>>>(x, Wu, bu, Wv, bv, out);
    kB<<<2 * sms, 256, SMEMB>>>(e, We, edge_index, out);
}